// round 4
// baseline (speedup 1.0000x reference)
#include <cuda_runtime.h>

#define DIM    1024
#define NPAIRS 512
#define NLAYER 10

// Precomputed composite butterfly coefficients per pair:
// (Re W, Im W, |W|^2, unused). 512 * 16B = 8 KB.
__device__ float4 g_W[NPAIRS];

// The 9 active butterfly layers each act on adjacent pair (u0,u1) as
// [[a,b],[-b,a]], i.e. complex multiply by (a - i b). Compose them.
__global__ void precompute_W_kernel(const float* __restrict__ params) {
    int k = threadIdx.x;             // pair index 0..511
    float A = 1.0f, B = 0.0f;        // accumulated W = A + iB
    int off = 2 * DIM;               // layer 0 (bs=1) is skipped but consumes 2*1024 params
#pragma unroll
    for (int l = 1; l < NLAYER; ++l) {
        int blk = k >> (l - 1);      // block index at layer l (bs = 2^l, block = 2k / bs)
        float a = params[off + 2 * blk];
        float b = params[off + 2 * blk + 1];
        // (A + iB) * (a - i b)
        float nA = A * a + B * b;
        float nB = B * a - A * b;
        A = nA; B = nB;
        off += 2 * (DIM >> l);
    }
    g_W[k] = make_float4(A, B, A * A + B * B, 0.0f);
}

// One block per row. 256 threads, each owns one float4 = pairs (2t, 2t+1).
// out = tanh(m)/m * s1 * (W_k applied per pair), with
//   s1 = atanh(||x||)/||x||,  m = s1 * sqrt(sum_k |W_k|^2 (x0^2+x1^2)).
__global__ void __launch_bounds__(256, 8)
hyper_butterfly_kernel(const float* __restrict__ x, float* __restrict__ out) {
    const int row = blockIdx.x;
    const int t = threadIdx.x;

    const float4 xv = reinterpret_cast<const float4*>(x + (size_t)row * DIM)[t];
    const float4 w0 = g_W[2 * t];
    const float4 w1 = g_W[2 * t + 1];

    const float p0 = xv.x * xv.x + xv.y * xv.y;
    const float p1 = xv.z * xv.z + xv.w * xv.w;
    float r0 = p0 + p1;                  // partial ||x||^2
    float r1 = w0.z * p0 + w1.z * p1;    // partial ||butterfly(x)||^2

    // warp reduce both sums
#pragma unroll
    for (int o = 16; o; o >>= 1) {
        r0 += __shfl_xor_sync(0xffffffffu, r0, o);
        r1 += __shfl_xor_sync(0xffffffffu, r1, o);
    }

    __shared__ float sm0[8], sm1[8];
    __shared__ float s_scale;
    const int wid = t >> 5, lane = t & 31;
    if (lane == 0) { sm0[wid] = r0; sm1[wid] = r1; }
    __syncthreads();

    if (t == 0) {
        float R0 = 0.0f, R1 = 0.0f;
#pragma unroll
        for (int i = 0; i < 8; ++i) { R0 += sm0[i]; R1 += sm1[i]; }
        const float n = sqrtf(R0);
        const float s1 = (n > 1e-12f) ? (atanhf(n) / n) : 1.0f;
        const float m = s1 * sqrtf(R1);
        const float s2 = (m > 1e-12f) ? (tanhf(m) / m) : 1.0f;
        s_scale = s1 * s2;
    }
    __syncthreads();
    const float s = s_scale;

    // apply composite complex rotation per pair, scale, store
    float4 o;
    o.x = s * (w0.x * xv.x - w0.y * xv.y);
    o.y = s * (w0.x * xv.y + w0.y * xv.x);
    o.z = s * (w1.x * xv.z - w1.y * xv.w);
    o.w = s * (w1.x * xv.w + w1.y * xv.z);
    reinterpret_cast<float4*>(out + (size_t)row * DIM)[t] = o;
}

extern "C" void kernel_launch(void* const* d_in, const int* in_sizes, int n_in,
                              void* d_out, int out_size) {
    const float* x      = (const float*)d_in[0];
    const float* params = (const float*)d_in[1];
    float* out          = (float*)d_out;

    const int rows = in_sizes[0] / DIM;   // 32768

    precompute_W_kernel<<<1, NPAIRS>>>(params);
    hyper_butterfly_kernel<<<rows, 256>>>(x, out);
}

// round 5
// speedup vs baseline: 1.2007x; 1.2007x over previous
#include <cuda_runtime.h>

#define DIM    1024
#define NPAIRS 512
#define NLAYER 10

// Composite butterfly coefficients, split by use:
//  g_Wri[k] = (Re W_k, Im W_k)   -> read as float4 per 2-pair chunk (store pass)
//  g_Wz[k]  = |W_k|^2            -> read as float2 per 2-pair chunk (norm pass)
__device__ __align__(16) float2 g_Wri[NPAIRS];
__device__ __align__(16) float  g_Wz[NPAIRS];

// The 9 active butterfly layers act on adjacent pair (u0,u1) as [[a,b],[-b,a]],
// i.e. complex multiply by (a - i b). Compose all layers into one W per pair.
__global__ void precompute_W_kernel(const float* __restrict__ params) {
    int k = threadIdx.x;             // pair index 0..511
    float A = 1.0f, B = 0.0f;
    int off = 2 * DIM;               // layer 0 (bs=1) skipped, consumes 2*1024 params
#pragma unroll
    for (int l = 1; l < NLAYER; ++l) {
        int blk = k >> (l - 1);
        float a = params[off + 2 * blk];
        float b = params[off + 2 * blk + 1];
        float nA = A * a + B * b;    // (A+iB)*(a-ib)
        float nB = B * a - A * b;
        A = nA; B = nB;
        off += 2 * (DIM >> l);
    }
    g_Wri[k] = make_float2(A, B);
    g_Wz[k]  = A * A + B * B;
}

// Warp-per-row: 8 rows per 256-thread CTA. Each lane owns 8 float4 chunks
// (chunk c = lane + 32*j). No shared memory, no __syncthreads — reduction is
// warp-shuffle only; every lane computes the scale redundantly.
__global__ void __launch_bounds__(256)
hyper_butterfly_kernel(const float* __restrict__ x, float* __restrict__ out) {
    const int warp = threadIdx.x >> 5;
    const int lane = threadIdx.x & 31;
    const int row  = (blockIdx.x << 3) + warp;

    const float4* __restrict__ xr = reinterpret_cast<const float4*>(x + (size_t)row * DIM);
    float4* __restrict__ orow     = reinterpret_cast<float4*>(out + (size_t)row * DIM);

    // Front-batched loads of x (MLP=8), then ||x||^2 partial — needs no W yet.
    float4 xv[8];
#pragma unroll
    for (int j = 0; j < 8; ++j) xv[j] = xr[lane + 32 * j];

    float r0 = 0.0f;
#pragma unroll
    for (int j = 0; j < 8; ++j)
        r0 += xv[j].x * xv[j].x + xv[j].y * xv[j].y
            + xv[j].z * xv[j].z + xv[j].w * xv[j].w;

    // PDL: wait for precompute_W_kernel's writes to be visible before touching W.
    cudaGridDependencySynchronize();

    const float2* __restrict__ wzp = reinterpret_cast<const float2*>(g_Wz);
    float r1 = 0.0f;
#pragma unroll
    for (int j = 0; j < 8; ++j) {
        float2 wz = wzp[lane + 32 * j];
        r1 += wz.x * (xv[j].x * xv[j].x + xv[j].y * xv[j].y)
            + wz.y * (xv[j].z * xv[j].z + xv[j].w * xv[j].w);
    }

    // Warp butterfly reduce both sums; all lanes end with the totals.
#pragma unroll
    for (int o = 16; o; o >>= 1) {
        r0 += __shfl_xor_sync(0xffffffffu, r0, o);
        r1 += __shfl_xor_sync(0xffffffffu, r1, o);
    }

    const float n  = sqrtf(r0);
    const float s1 = atanhf(n) / fmaxf(n, 1e-12f);
    const float m  = s1 * sqrtf(r1);
    const float s  = s1 * tanhf(m) / fmaxf(m, 1e-12f);

    // Apply composite complex rotation per pair, scale, store.
    const float4* __restrict__ wrip = reinterpret_cast<const float4*>(g_Wri);
#pragma unroll
    for (int j = 0; j < 8; ++j) {
        float4 w = wrip[lane + 32 * j];
        float4 o4;
        o4.x = s * (w.x * xv[j].x - w.y * xv[j].y);
        o4.y = s * (w.x * xv[j].y + w.y * xv[j].x);
        o4.z = s * (w.z * xv[j].z - w.w * xv[j].w);
        o4.w = s * (w.z * xv[j].w + w.w * xv[j].z);
        orow[lane + 32 * j] = o4;
    }
}

extern "C" void kernel_launch(void* const* d_in, const int* in_sizes, int n_in,
                              void* d_out, int out_size) {
    const float* x      = (const float*)d_in[0];
    const float* params = (const float*)d_in[1];
    float* out          = (float*)d_out;

    const int rows = in_sizes[0] / DIM;   // 32768

    precompute_W_kernel<<<1, NPAIRS>>>(params);

    // Main kernel with programmatic dependent launch: its x-load prologue
    // overlaps the (tiny) precompute kernel; cudaGridDependencySynchronize()
    // in-kernel orders the W reads.
    cudaLaunchConfig_t cfg = {};
    cfg.gridDim  = dim3(rows >> 3);
    cfg.blockDim = dim3(256);
    cfg.dynamicSmemBytes = 0;
    cfg.stream = 0;
    cudaLaunchAttribute attr[1];
    attr[0].id = cudaLaunchAttributeProgrammaticStreamSerialization;
    attr[0].val.programmaticStreamSerializationAllowed = 1;
    cfg.attrs = attr;
    cfg.numAttrs = 1;
    cudaLaunchKernelEx(&cfg, hyper_butterfly_kernel, x, out);
}